// round 1
// baseline (speedup 1.0000x reference)
#include <cuda_runtime.h>
#include <cstdint>

// Problem constants (fixed by the dataset)
#define NPT   120000
#define HID   128
#define INP   320
#define CIN   448      // HID + INP
#define KOFF  28       // 27 conv offsets + 1 point-transform slot
#define NZR   256      // fused z|r output width

// -------- device scratch (no allocations allowed) --------
__device__ float g_HX [(size_t)NPT * CIN];     // concat(h, x)
__device__ float g_RX [(size_t)NPT * CIN];     // concat(r*h, x)
__device__ float g_Z  [(size_t)NPT * HID];     // sigmoid(z_pre)
__device__ float g_Wzr[(size_t)KOFF * CIN * NZR]; // fused [k][cin][z|r]
__device__ float g_Wq [(size_t)KOFF * CIN * HID]; // [k][cin][q]

__device__ __forceinline__ float to_tf32(float x) {
    float r;
    asm("cvt.rna.tf32.f32 %0, %1;" : "=f"(r) : "f"(x));
    return r;
}

__device__ __forceinline__ void mma_tf32(float* d, const uint32_t* a, const uint32_t* b) {
    asm volatile(
        "mma.sync.aligned.m16n8k8.row.col.f32.tf32.tf32.f32 "
        "{%0,%1,%2,%3}, {%4,%5,%6,%7}, {%8,%9}, {%0,%1,%2,%3};"
        : "+f"(d[0]), "+f"(d[1]), "+f"(d[2]), "+f"(d[3])
        : "r"(a[0]), "r"(a[1]), "r"(a[2]), "r"(a[3]), "r"(b[0]), "r"(b[1]));
}

// -------- packing kernels --------
__global__ void pack_inputs(const float* __restrict__ h, const float* __restrict__ x, int N) {
    size_t idx = (size_t)blockIdx.x * blockDim.x + threadIdx.x;
    size_t total = (size_t)N * CIN;
    if (idx >= total) return;
    int c = (int)(idx % CIN);
    size_t n = idx / CIN;
    float v = (c < HID) ? h[n * HID + c] : x[n * INP + (c - HID)];
    g_HX[idx] = v;
    if (c >= HID) g_RX[idx] = v;   // x-tail of rx; r*h part written by pass 1
}

__global__ void pack_wzr(const float* __restrict__ Wz, const float* __restrict__ Wz_pt,
                         const float* __restrict__ Wr, const float* __restrict__ Wr_pt) {
    size_t idx = (size_t)blockIdx.x * blockDim.x + threadIdx.x;
    size_t total = (size_t)KOFF * CIN * NZR;
    if (idx >= total) return;
    int n = (int)(idx % NZR);
    int c = (int)((idx / NZR) % CIN);
    int k = (int)(idx / ((size_t)NZR * CIN));
    float v;
    if (k < 27) {
        v = (n < HID) ? Wz[((size_t)k * CIN + c) * HID + n]
                      : Wr[((size_t)k * CIN + c) * HID + (n - HID)];
    } else {
        v = (n < HID) ? Wz_pt[(size_t)c * HID + n]
                      : Wr_pt[(size_t)c * HID + (n - HID)];
    }
    g_Wzr[idx] = v;
}

__global__ void pack_wq(const float* __restrict__ Wq, const float* __restrict__ Wq_pt) {
    size_t idx = (size_t)blockIdx.x * blockDim.x + threadIdx.x;
    size_t total = (size_t)KOFF * CIN * HID;
    if (idx >= total) return;
    int n = (int)(idx % HID);
    int c = (int)((idx / HID) % CIN);
    int k = (int)(idx / ((size_t)HID * CIN));
    g_Wq[idx] = (k < 27) ? Wq[((size_t)k * CIN + c) * HID + n]
                         : Wq_pt[(size_t)c * HID + n];
}

// -------- core sconv GEMM --------
// PASS = 1: A = g_HX, W = g_Wzr (wstride 256), blockIdx.y in {0 (z), 1 (r)}
//           epilogue: sigmoid -> g_Z / g_RX[:, :128] = r*h
// PASS = 2: A = g_RX, W = g_Wq (wstride 128)
//           epilogue: q = tanh, out = (1-z)*h + z*q
template <int PASS>
__global__ void __launch_bounds__(256, 2)
sconv_kernel(const int* __restrict__ nbr, const float* __restrict__ h,
             const float* __restrict__ bias0, const float* __restrict__ bias1,
             float* __restrict__ out, int N) {
    constexpr int BM = 128;
    const int tid  = threadIdx.x;
    const int wid  = tid >> 5;
    const int lane = tid & 31;
    const int wm   = wid >> 2;        // 0..1  (64 rows each)
    const int wn   = wid & 3;         // 0..3  (32 cols each)
    const int grp  = lane >> 2;       // 0..7
    const int tg   = lane & 3;        // 0..3

    const int i0 = blockIdx.x * BM;
    const int ct = (PASS == 1) ? (int)blockIdx.y : 0;
    const int colbase = ct * 128;
    const float* __restrict__ Asrc = (PASS == 1) ? g_HX : g_RX;
    const float* __restrict__ W    = (PASS == 1) ? g_Wzr : g_Wq;
    const int wstride = (PASS == 1) ? NZR : HID;

    __shared__ __align__(16) float As[128][36];
    __shared__ __align__(16) float Bs[32][132];
    __shared__ int sidx[128];

    float acc[4][4][4];
#pragma unroll
    for (int a = 0; a < 4; ++a)
#pragma unroll
        for (int b = 0; b < 4; ++b)
#pragma unroll
            for (int c = 0; c < 4; ++c) acc[a][b][c] = 0.f;

    for (int k = 0; k < KOFF; ++k) {
        if (tid < 128) {
            int gr = i0 + tid;
            int id;
            if (gr >= N)        id = -1;
            else if (k == 27)   id = gr;                 // point-transform slot
            else                id = nbr[(size_t)gr * 27 + k];
            sidx[tid] = id;
        }
        __syncthreads();

        for (int cc = 0; cc < CIN; cc += 32) {
            // ---- load A tile (gathered, masked -> zeros) ----
#pragma unroll
            for (int it = 0; it < 4; ++it) {
                int row = it * 32 + (tid >> 3);
                int c4  = (tid & 7) * 4;
                int id  = sidx[row];
                float4 v;
                if (id >= 0)
                    v = *reinterpret_cast<const float4*>(Asrc + (size_t)id * CIN + cc + c4);
                else
                    v = make_float4(0.f, 0.f, 0.f, 0.f);
                float4 w;
                w.x = to_tf32(v.x); w.y = to_tf32(v.y);
                w.z = to_tf32(v.z); w.w = to_tf32(v.w);
                *reinterpret_cast<float4*>(&As[row][c4]) = w;
            }
            // ---- load B tile (weights) ----
#pragma unroll
            for (int j = 0; j < 4; ++j) {
                int fidx = tid + j * 256;            // 0..1023
                int brow = fidx >> 5;                // 0..31
                int bc4  = (fidx & 31) * 4;          // 0..124
                float4 v = *reinterpret_cast<const float4*>(
                    W + ((size_t)k * CIN + cc + brow) * wstride + colbase + bc4);
                float4 w;
                w.x = to_tf32(v.x); w.y = to_tf32(v.y);
                w.z = to_tf32(v.z); w.w = to_tf32(v.w);
                *reinterpret_cast<float4*>(&Bs[brow][bc4]) = w;
            }
            __syncthreads();

            // ---- mma over 4 k-steps of 8 ----
#pragma unroll
            for (int kk = 0; kk < 4; ++kk) {
                uint32_t af[4][4];
#pragma unroll
                for (int mt = 0; mt < 4; ++mt) {
                    int r = wm * 64 + mt * 16 + grp;
                    af[mt][0] = __float_as_uint(As[r    ][kk * 8 + tg    ]);
                    af[mt][1] = __float_as_uint(As[r + 8][kk * 8 + tg    ]);
                    af[mt][2] = __float_as_uint(As[r    ][kk * 8 + tg + 4]);
                    af[mt][3] = __float_as_uint(As[r + 8][kk * 8 + tg + 4]);
                }
                uint32_t bf[4][2];
#pragma unroll
                for (int nt = 0; nt < 4; ++nt) {
                    int c = wn * 32 + nt * 8 + grp;
                    bf[nt][0] = __float_as_uint(Bs[kk * 8 + tg    ][c]);
                    bf[nt][1] = __float_as_uint(Bs[kk * 8 + tg + 4][c]);
                }
#pragma unroll
                for (int mt = 0; mt < 4; ++mt)
#pragma unroll
                    for (int nt = 0; nt < 4; ++nt)
                        mma_tf32(acc[mt][nt], af[mt], bf[nt]);
            }
            __syncthreads();
        }
    }

    // ---- epilogue ----
#pragma unroll
    for (int mt = 0; mt < 4; ++mt) {
#pragma unroll
        for (int nt = 0; nt < 4; ++nt) {
            int lc = wn * 32 + nt * 8 + tg * 2;      // 0..127 local col
#pragma unroll
            for (int half = 0; half < 2; ++half) {
                int r = i0 + wm * 64 + mt * 16 + grp + half * 8;
                if (r >= N) continue;
#pragma unroll
                for (int e = 0; e < 2; ++e) {
                    float v = acc[mt][nt][half * 2 + e];
                    int col = lc + e;
                    if (PASS == 1) {
                        const float* bias = (ct == 0) ? bias0 : bias1;
                        float s = 1.f / (1.f + expf(-(v + bias[col])));
                        if (ct == 0) g_Z[(size_t)r * HID + col] = s;
                        else         g_RX[(size_t)r * CIN + col] = s * h[(size_t)r * HID + col];
                    } else {
                        float q  = tanhf(v + bias0[col]);
                        float z  = g_Z[(size_t)r * HID + col];
                        float hv = h[(size_t)r * HID + col];
                        out[(size_t)r * HID + col] = (1.f - z) * hv + z * q;
                    }
                }
            }
        }
    }
}

extern "C" void kernel_launch(void* const* d_in, const int* in_sizes, int n_in,
                              void* d_out, int out_size) {
    const float* h     = (const float*)d_in[0];
    const float* x     = (const float*)d_in[1];
    const int*   nbr   = (const int*)  d_in[2];
    const float* Wz    = (const float*)d_in[3];
    const float* Wz_pt = (const float*)d_in[4];
    const float* bz    = (const float*)d_in[5];
    const float* Wr    = (const float*)d_in[6];
    const float* Wr_pt = (const float*)d_in[7];
    const float* br    = (const float*)d_in[8];
    const float* Wq    = (const float*)d_in[9];
    const float* Wq_pt = (const float*)d_in[10];
    const float* bq    = (const float*)d_in[11];

    const int N = in_sizes[0] / HID;

    {
        size_t total = (size_t)N * CIN;
        pack_inputs<<<(unsigned)((total + 255) / 256), 256>>>(h, x, N);
    }
    {
        size_t total = (size_t)KOFF * CIN * NZR;
        pack_wzr<<<(unsigned)((total + 255) / 256), 256>>>(Wz, Wz_pt, Wr, Wr_pt);
    }
    {
        size_t total = (size_t)KOFF * CIN * HID;
        pack_wq<<<(unsigned)((total + 255) / 256), 256>>>(Wq, Wq_pt);
    }

    dim3 g1((N + 127) / 128, 2);
    sconv_kernel<1><<<g1, 256>>>(nbr, h, bz, br, nullptr, N);

    dim3 g2((N + 127) / 128, 1);
    sconv_kernel<2><<<g2, 256>>>(nbr, h, bq, nullptr, (float*)d_out, N);
}

// round 3
// speedup vs baseline: 3.9368x; 3.9368x over previous
#include <cuda_runtime.h>
#include <cuda_fp16.h>
#include <cstdint>

#define NPT   120000
#define HID   128
#define INP   320
#define CINL  448
#define KOFF  28
#define KTOT  (KOFF * CINL)     // 12544
#define NCHUNK (KOFF * 7)       // 196 chunks of K=64
#define STAGE_BYTES 32768       // 16KB A (128x128B) + 16KB B (128x128B)

// ---------------- device scratch ----------------
__device__ __half g_HX [(size_t)NPT * CINL];
__device__ __half g_RX [(size_t)NPT * CINL];
__device__ float  g_Z  [(size_t)NPT * HID];
__device__ __half g_Wzr[(size_t)256 * KTOT];   // [n][k*448+c]  n<128: z, n>=128: r
__device__ __half g_Wq [(size_t)128 * KTOT];   // [n][k*448+c]

// ---------------- asm helpers ----------------
__device__ __forceinline__ uint32_t smem_u32(const void* p) {
    uint32_t a;
    asm("{ .reg .u64 t; cvta.to.shared.u64 t, %1; cvt.u32.u64 %0, t; }" : "=r"(a) : "l"(p));
    return a;
}
__device__ __forceinline__ void cp16(uint32_t dst, const void* src, int sz) {
    asm volatile("cp.async.cg.shared.global [%0], [%1], 16, %2;"
                 :: "r"(dst), "l"(src), "r"(sz) : "memory");
}
#define CP_COMMIT() asm volatile("cp.async.commit_group;" ::: "memory")
#define CP_WAIT1()  asm volatile("cp.async.wait_group 1;" ::: "memory")

#define LDSM_X4(r0, r1, r2, r3, addr) \
    asm volatile("ldmatrix.sync.aligned.m8n8.x4.shared.b16 {%0,%1,%2,%3}, [%4];" \
        : "=r"(r0), "=r"(r1), "=r"(r2), "=r"(r3) : "r"(addr))

__device__ __forceinline__ void mma16816(float* d, const uint32_t* a, uint32_t b0, uint32_t b1) {
    asm volatile(
        "mma.sync.aligned.m16n8k16.row.col.f32.f16.f16.f32 "
        "{%0,%1,%2,%3}, {%4,%5,%6,%7}, {%8,%9}, {%0,%1,%2,%3};"
        : "+f"(d[0]), "+f"(d[1]), "+f"(d[2]), "+f"(d[3])
        : "r"(a[0]), "r"(a[1]), "r"(a[2]), "r"(a[3]), "r"(b0), "r"(b1));
}

// ---------------- packing kernels ----------------
__global__ void pack_inputs(const float* __restrict__ h, const float* __restrict__ x, int N) {
    size_t idx = (size_t)blockIdx.x * blockDim.x + threadIdx.x;
    size_t total = (size_t)N * CINL;
    if (idx >= total) return;
    int c = (int)(idx % CINL);
    size_t n = idx / CINL;
    float v = (c < HID) ? h[n * HID + c] : x[n * INP + (c - HID)];
    __half hv = __float2half_rn(v);
    g_HX[idx] = hv;
    if (c >= HID) g_RX[idx] = hv;
}

__global__ void pack_wzr(const float* __restrict__ Wz, const float* __restrict__ Wz_pt,
                         const float* __restrict__ Wr, const float* __restrict__ Wr_pt) {
    size_t idx = (size_t)blockIdx.x * blockDim.x + threadIdx.x;
    size_t total = (size_t)256 * KTOT;
    if (idx >= total) return;
    int rem = (int)(idx % KTOT);
    int n = (int)(idx / KTOT);
    int k = rem / CINL;
    int c = rem % CINL;
    float v;
    if (n < HID) v = (k < 27) ? Wz[((size_t)k * CINL + c) * HID + n] : Wz_pt[(size_t)c * HID + n];
    else {
        int m = n - HID;
        v = (k < 27) ? Wr[((size_t)k * CINL + c) * HID + m] : Wr_pt[(size_t)c * HID + m];
    }
    g_Wzr[idx] = __float2half_rn(v);
}

__global__ void pack_wq(const float* __restrict__ Wq, const float* __restrict__ Wq_pt) {
    size_t idx = (size_t)blockIdx.x * blockDim.x + threadIdx.x;
    size_t total = (size_t)128 * KTOT;
    if (idx >= total) return;
    int rem = (int)(idx % KTOT);
    int n = (int)(idx / KTOT);
    int k = rem / CINL;
    int c = rem % CINL;
    float v = (k < 27) ? Wq[((size_t)k * CINL + c) * HID + n] : Wq_pt[(size_t)c * HID + n];
    g_Wq[idx] = __float2half_rn(v);
}

// ---------------- main GEMM kernel ----------------
// BM=128, BN=128, BK=64 halves. 8 warps = 2(M) x 4(N); warp tile 64x32.
// PASS 1: A=g_HX, B=g_Wzr row-block ct*128 (ct=blockIdx.y: 0=z, 1=r)
// PASS 2: A=g_RX, B=g_Wq
template <int PASS>
__global__ void __launch_bounds__(256, 2)
sconv_mma(const int* __restrict__ nbr, const float* __restrict__ h,
          const float* __restrict__ b0, const float* __restrict__ b1,
          float* __restrict__ out, int N) {
    extern __shared__ __align__(128) char dynsmem[];

    const int tid  = threadIdx.x;
    const int wid  = tid >> 5;
    const int lane = tid & 31;
    const int wm   = wid >> 2;          // 0..1
    const int wn   = wid & 3;           // 0..3
    const int grp  = lane >> 2;
    const int tg   = lane & 3;
    const int i0   = blockIdx.x * 128;
    const int ct   = (PASS == 1) ? (int)blockIdx.y : 0;

    const __half* __restrict__ Asrc = (PASS == 1) ? g_HX : g_RX;
    const __half* __restrict__ WB   = (PASS == 1) ? g_Wzr : g_Wq;
    const size_t  nbase = (size_t)ct * 128;

    const uint32_t dsm_raw = smem_u32(dynsmem);
    const uint32_t dsm = (dsm_raw + 127u) & ~127u;

    // ---- prefetch constants ----
    const int  prow  = tid >> 1;              // A row / B n-row (0..127)
    const int  pseg0 = (tid & 1) * 4;         // first 16B seg (of 8)
    const uint32_t pxm = (uint32_t)((prow & 7) << 4);
    const int  g = i0 + prow;
    const __half* pbrow = WB + (size_t)(nbase + prow) * KTOT;

    int    cur_k = -1;
    int    asz   = 0;
    size_t aoff  = 0;

    // ---- ldmatrix lane constants ----
    const int sel = lane >> 3;                      // 0..3
    const uint32_t lxm = (uint32_t)((lane & 7) << 4);
    const uint32_t a_row_off =
        (uint32_t)(wm * 64 + (sel & 1) * 8 + (lane & 7)) * 128;
    const uint32_t a_cs16 = (uint32_t)((sel >> 1) * 16);
    const uint32_t b_row_off =
        (uint32_t)(wn * 32 + (sel >> 1) * 8 + (lane & 7)) * 128;
    const uint32_t b_cs16 = (uint32_t)((sel & 1) * 16);

    float acc[4][4][4];
#pragma unroll
    for (int a = 0; a < 4; ++a)
#pragma unroll
        for (int b = 0; b < 4; ++b)
#pragma unroll
            for (int c = 0; c < 4; ++c) acc[a][b][c] = 0.f;

    // ---- prefetch lambda ----
    auto do_prefetch = [&](int j) {
        const int k  = j / 7;
        const int cc = (j % 7) * 64;
        const int s  = j % 3;
        if (k != cur_k) {
            cur_k = k;
            int id = -1;
            if (g < N) id = (k == 27) ? g : nbr[(size_t)g * 27 + k];
            asz  = (id >= 0) ? 16 : 0;
            aoff = (size_t)((id >= 0) ? id : 0) * CINL;
        }
        const uint32_t sb = dsm + s * STAGE_BYTES;
        const __half* pa = Asrc + aoff + cc + pseg0 * 8;
        const __half* pb = pbrow + (size_t)k * CINL + cc + pseg0 * 8;
        const uint32_t da = sb + (uint32_t)prow * 128;
        const uint32_t db = sb + 16384 + (uint32_t)prow * 128;
#pragma unroll
        for (int t = 0; t < 4; ++t) {
            const uint32_t so = (uint32_t)(((pseg0 + t) * 16)) ^ pxm;
            cp16(da + so, pa + t * 8, asz);
            cp16(db + so, pb + t * 8, 16);
        }
    };

    do_prefetch(0); CP_COMMIT();
    do_prefetch(1); CP_COMMIT();

    for (int i = 0; i < NCHUNK; ++i) {
        CP_WAIT1();
        __syncthreads();

        const uint32_t sb = dsm + (i % 3) * STAGE_BYTES;
        const uint32_t aB = sb + a_row_off;
        const uint32_t bB = sb + 16384 + b_row_off;

#pragma unroll
        for (int ks = 0; ks < 4; ++ks) {
            const uint32_t acol = (uint32_t)(ks * 32 + a_cs16) ^ lxm;
            const uint32_t bcol = (uint32_t)(ks * 32 + b_cs16) ^ lxm;
            uint32_t bfr[2][4];
            LDSM_X4(bfr[0][0], bfr[0][1], bfr[0][2], bfr[0][3], bB + bcol);
            LDSM_X4(bfr[1][0], bfr[1][1], bfr[1][2], bfr[1][3], bB + 2048 + bcol);
#pragma unroll
            for (int mt = 0; mt < 4; ++mt) {
                uint32_t afr[4];
                LDSM_X4(afr[0], afr[1], afr[2], afr[3], aB + mt * 2048 + acol);
#pragma unroll
                for (int p = 0; p < 2; ++p) {
                    mma16816(acc[mt][2 * p],     afr, bfr[p][0], bfr[p][1]);
                    mma16816(acc[mt][2 * p + 1], afr, bfr[p][2], bfr[p][3]);
                }
            }
        }

        if (i + 2 < NCHUNK) do_prefetch(i + 2);
        CP_COMMIT();
    }

    // ---- epilogue ----
#pragma unroll
    for (int mt = 0; mt < 4; ++mt) {
#pragma unroll
        for (int nt = 0; nt < 4; ++nt) {
            const int lc = wn * 32 + nt * 8 + tg * 2;
#pragma unroll
            for (int half = 0; half < 2; ++half) {
                const int r = i0 + wm * 64 + mt * 16 + grp + half * 8;
                if (r >= N) continue;
#pragma unroll
                for (int e = 0; e < 2; ++e) {
                    const float v = acc[mt][nt][half * 2 + e];
                    const int col = lc + e;
                    if (PASS == 1) {
                        const float bias = (ct == 0) ? __ldg(&b0[col]) : __ldg(&b1[col]);
                        const float s = 1.f / (1.f + __expf(-(v + bias)));
                        if (ct == 0) g_Z[(size_t)r * HID + col] = s;
                        else g_RX[(size_t)r * CINL + col] =
                                 __float2half_rn(s * h[(size_t)r * HID + col]);
                    } else {
                        const float q  = tanhf(v + __ldg(&b0[col]));
                        const float z  = g_Z[(size_t)r * HID + col];
                        const float hv = h[(size_t)r * HID + col];
                        out[(size_t)r * HID + col] = fmaf(z, q - hv, hv);
                    }
                }
            }
        }
    }
}

// ---------------- launch ----------------
extern "C" void kernel_launch(void* const* d_in, const int* in_sizes, int n_in,
                              void* d_out, int out_size) {
    const float* h     = (const float*)d_in[0];
    const float* x     = (const float*)d_in[1];
    const int*   nbr   = (const int*)  d_in[2];
    const float* Wz    = (const float*)d_in[3];
    const float* Wz_pt = (const float*)d_in[4];
    const float* bz    = (const float*)d_in[5];
    const float* Wr    = (const float*)d_in[6];
    const float* Wr_pt = (const float*)d_in[7];
    const float* br    = (const float*)d_in[8];
    const float* Wq    = (const float*)d_in[9];
    const float* Wq_pt = (const float*)d_in[10];
    const float* bq    = (const float*)d_in[11];

    const int N = in_sizes[0] / HID;
    const int SMEM = 3 * STAGE_BYTES + 128;   // 98432

    cudaFuncSetAttribute(sconv_mma<1>, cudaFuncAttributeMaxDynamicSharedMemorySize, SMEM);
    cudaFuncSetAttribute(sconv_mma<2>, cudaFuncAttributeMaxDynamicSharedMemorySize, SMEM);

    {
        size_t total = (size_t)N * CINL;
        pack_inputs<<<(unsigned)((total + 255) / 256), 256>>>(h, x, N);
    }
    {
        size_t total = (size_t)256 * KTOT;
        pack_wzr<<<(unsigned)((total + 255) / 256), 256>>>(Wz, Wz_pt, Wr, Wr_pt);
    }
    {
        size_t total = (size_t)128 * KTOT;
        pack_wq<<<(unsigned)((total + 255) / 256), 256>>>(Wq, Wq_pt);
    }

    dim3 g1((N + 127) / 128, 2);
    sconv_mma<1><<<g1, 256, SMEM>>>(nbr, h, bz, br, nullptr, N);

    dim3 g2((N + 127) / 128, 1);
    sconv_mma<2><<<g2, 256, SMEM>>>(nbr, h, bq, nullptr, (float*)d_out, N);
}